// round 14
// baseline (speedup 1.0000x reference)
#include <cuda_runtime.h>
#include <cuda_bf16.h>
#include <cstdint>

#define DT       0.0166667f
#define SLOPE    0.01f
#define NN_RATIO 0.5f
#define THREADS  128
#define PASSES   4

// bf16x2 constant 0.01 (0x3C24 per half)
#define SLOPE2   0x3C243C24u

struct __align__(16) Smem {
    __nv_bfloat16 wt1[2][32][20];   // W1^T: k<2 *Ms, k==2 alpha row, k==3 = b1, rest 0
    __nv_bfloat16 wt2[2][32][40];   // W2^T padded: [m][o][i]
    __nv_bfloat16 wt3[2][32][40];   // W3^T padded
    uint32_t w4b[2][16];            // w4 packed bf16x2
    float b2[2][32], b3[2][32], b4[2];
};

__device__ __forceinline__ float tanh_fast(float x) {
    float y; asm("tanh.approx.f32 %0, %1;" : "=f"(y) : "f"(x)); return y;
}
__device__ __forceinline__ uint32_t pkbf(float lo, float hi) {
    uint32_t r; asm("cvt.rn.bf16x2.f32 %0, %1, %2;" : "=r"(r) : "f"(hi), "f"(lo)); return r;
}
// packed leaky relu on bf16x2: max(x, 0.01*x)
__device__ __forceinline__ uint32_t lk2(uint32_t x) {
    uint32_t y, r;
    asm("mul.rn.bf16x2 %0, %1, %2;" : "=r"(y) : "r"(x), "r"(SLOPE2));
    asm("max.bf16x2 %0, %1, %2;"    : "=r"(r) : "r"(x), "r"(y));
    return r;
}
__device__ __forceinline__ uint32_t lkpk(float a, float b) { return lk2(pkbf(a, b)); }

__device__ __forceinline__ void mma16816(float* d,
    uint32_t a0, uint32_t a1, uint32_t a2, uint32_t a3,
    uint32_t b0, uint32_t b1,
    float c0, float c1, float c2, float c3)
{
    asm volatile(
        "mma.sync.aligned.m16n8k16.row.col.f32.bf16.bf16.f32 "
        "{%0,%1,%2,%3},{%4,%5,%6,%7},{%8,%9},{%10,%11,%12,%13};"
        : "=f"(d[0]), "=f"(d[1]), "=f"(d[2]), "=f"(d[3])
        : "r"(a0), "r"(a1), "r"(a2), "r"(a3), "r"(b0), "r"(b1),
          "f"(c0), "f"(c1), "f"(c2), "f"(c3));
}

// SSout = e^A*SS + phi1(A)*[0, B10*DT]^T  (closed form of the 6x6 expm)
__device__ __forceinline__ float2 integrate(float ss0, float ss1, float Ktot, float Bsum,
                                            float invI0, float I0, float B0p, float K0p) {
    const float A10 = -(Ktot + K0p) * invI0;
    const float Dd  = 2.0f * sqrtf(Ktot * I0);
    const float A11 = -(Dd + B0p) * invI0;
    const float B10 = Bsum * invI0;
    const float a01 = DT, a10 = A10 * DT, a11 = A11 * DT;

    float T00 = 1.f, T01 = 0.f, T10 = 0.f, T11 = 1.f;
    float E00 = 1.f, E01 = 0.f, E10 = 0.f, E11 = 1.f;
    float P01 = 0.f, P11 = 1.f;
    #pragma unroll
    for (int k = 1; k <= 6; k++) {
        const float r   = 1.0f / (float)k;
        const float n00 = (T01 * a10) * r;
        const float n01 = (T00 * a01 + T01 * a11) * r;
        const float n10 = (T11 * a10) * r;
        const float n11 = (T10 * a01 + T11 * a11) * r;
        T00 = n00; T01 = n01; T10 = n10; T11 = n11;
        E00 += T00; E01 += T01; E10 += T10; E11 += T11;
        const float r2 = 1.0f / (float)(k + 1);
        P01 = fmaf(T01, r2, P01);
        P11 = fmaf(T11, r2, P11);
    }
    const float cx = B10 * DT;
    float2 o;
    o.x = E00 * ss0 + E01 * ss1 + P01 * cx;
    o.y = E10 * ss0 + E11 * ss1 + P11 * cx;
    return o;
}

__global__ void __launch_bounds__(THREADS, 4) joint_mma_kernel(
    const float* __restrict__ SS, const float* __restrict__ Alphas,
    const float* __restrict__ K0s, const float* __restrict__ K1s,
    const float* __restrict__ L0s, const float* __restrict__ L1s,
    const float* __restrict__ Ms,  const float* __restrict__ I_p,
    const float* __restrict__ B_p, const float* __restrict__ K_p,
    const float* __restrict__ W1, const float* __restrict__ b1g,
    const float* __restrict__ W2, const float* __restrict__ b2g,
    const float* __restrict__ W3, const float* __restrict__ b3g,
    const float* __restrict__ W4, const float* __restrict__ b4g,
    float* __restrict__ out, int B)
{
    __shared__ Smem sm;
    const int tid = threadIdx.x;

    // ---- Stage weights (transposed, bf16) ----
    // wt1 rows: k<2 = W1*Ms (Ms=+-1 exact), k==2 = W1 alpha row, k==3 = b1 (bias
    // rides K slot 3; A-fragment supplies constant 1.0 there), k>=4 zero
    for (int idx = tid; idx < 1024; idx += THREADS) {
        const int k = idx & 15, o = (idx >> 4) & 31, m = idx >> 9;
        float v = 0.0f;
        if (k < 3) {
            v = W1[m * 96 + k * 32 + o];
            if (k < 2) v *= __ldg(Ms + m);
        } else if (k == 3) {
            v = b1g[m * 32 + o];
        }
        sm.wt1[m][o][k] = __float2bfloat16(v);
    }
    for (int idx = tid; idx < 2048; idx += THREADS) {
        const int o = idx & 31, i = (idx >> 5) & 31, m = idx >> 10;
        sm.wt2[m][o][i] = __float2bfloat16(W2[idx]);
        sm.wt3[m][o][i] = __float2bfloat16(W3[idx]);
    }
    for (int idx = tid; idx < 64; idx += THREADS) {
        const int m = idx >> 5, o = idx & 31;
        sm.b2[m][o] = b2g[idx];
        sm.b3[m][o] = b3g[idx];
    }
    if (tid < 32) {
        const int m = tid >> 4, j = tid & 15;
        sm.w4b[m][j] = pkbf(W4[m * 32 + 2 * j], W4[m * 32 + 2 * j + 1]);
    }
    if (tid < 2) sm.b4[tid] = b4g[tid];
    __syncthreads();

    const int l  = tid & 31, w = tid >> 5;
    const int g  = l >> 2, tc = l & 3;
    const int own_row = g + 8 * tc;

    const float I0  = __ldg(I_p), B0p = __ldg(B_p), K0p = __ldg(K_p);
    const float invI0 = 1.0f / I0;

    // L4 B-fragments (col 0 = w4, cols 1-7 zero): only g==0 lanes hold data
    uint32_t w4f[2][4];
    #pragma unroll
    for (int m = 0; m < 2; m++) {
        w4f[m][0] = (g == 0) ? sm.w4b[m][tc]      : 0u;
        w4f[m][1] = (g == 0) ? sm.w4b[m][tc + 4]  : 0u;
        w4f[m][2] = (g == 0) ? sm.w4b[m][tc + 8]  : 0u;
        w4f[m][3] = (g == 0) ? sm.w4b[m][tc + 12] : 0u;
    }

    #pragma unroll 1
    for (int p = 0; p < PASSES; p++) {
        const int ebase = (blockIdx.x * PASSES + p) * 128 + w * 32;
        const int e = ebase + own_row;
        const float2 ss = ((const float2*)SS)[e];
        const float2 al = ((const float2*)Alphas)[e];
        const float al0 = __saturatef(al.x);
        const float al1 = __saturatef(al.y);

        const uint32_t ssb = pkbf(ss.x, ss.y);
        const uint32_t amb = pkbf(al0, al1);
        uint32_t ssj[4], amj[4];
        #pragma unroll
        for (int j = 0; j < 4; j++) {
            const int src = (l & ~3) + j;
            ssj[j] = __shfl_sync(0xffffffffu, ssb, src);
            amj[j] = __shfl_sync(0xffffffffu, amb, src);
        }

        // ---- Layer 1 A-fragments for BOTH muscles ----
        // tc==0 -> (ss0,ss1) @ k0,k1 ; tc==1 -> (alpha_m, 1.0) @ k2,k3
        uint32_t A1f[2][2][2];
        #pragma unroll
        for (int m = 0; m < 2; m++) {
            #pragma unroll
            for (int mt = 0; mt < 2; mt++) {
                #pragma unroll
                for (int jj = 0; jj < 2; jj++) {
                    const int j = 2 * mt + jj;
                    uint32_t v = 0u;
                    if (tc == 0)      v = ssj[j];
                    else if (tc == 1) v = (m ? (amj[j] >> 16) : (amj[j] & 0xFFFFu))
                                          | 0x3F800000u;
                    A1f[m][mt][jj] = v;
                }
            }
        }

        float d[2][2][4][4];       // [m][mt][nt][reg]
        uint32_t A2[2][2][2][4];   // [m][mt][kt][reg]

        // ---- Layer 1 mma (both muscles interleaved), C = 0 ----
        #pragma unroll
        for (int m = 0; m < 2; m++) {
            #pragma unroll
            for (int nt = 0; nt < 4; nt++) {
                const int n = nt * 8 + g;
                const uint32_t b0  = *(const uint32_t*)&sm.wt1[m][n][2 * tc];
                const uint32_t b1f = *(const uint32_t*)&sm.wt1[m][n][2 * tc + 8];
                #pragma unroll
                for (int mt = 0; mt < 2; mt++)
                    mma16816(d[m][mt][nt], A1f[m][mt][0], A1f[m][mt][1], 0u, 0u,
                             b0, b1f, 0.f, 0.f, 0.f, 0.f);
            }
        }

        // ---- Layers 2 and 3 (both muscles live concurrently) ----
        #pragma unroll
        for (int L = 0; L < 2; L++) {
            #pragma unroll
            for (int m = 0; m < 2; m++) {
                #pragma unroll
                for (int mt = 0; mt < 2; mt++) {
                    #pragma unroll
                    for (int kt = 0; kt < 2; kt++) {
                        const int na = 2 * kt, nb = 2 * kt + 1;
                        A2[m][mt][kt][0] = lkpk(d[m][mt][na][0], d[m][mt][na][1]);
                        A2[m][mt][kt][1] = lkpk(d[m][mt][na][2], d[m][mt][na][3]);
                        A2[m][mt][kt][2] = lkpk(d[m][mt][nb][0], d[m][mt][nb][1]);
                        A2[m][mt][kt][3] = lkpk(d[m][mt][nb][2], d[m][mt][nb][3]);
                    }
                }
            }
            #pragma unroll
            for (int m = 0; m < 2; m++) {
                const __nv_bfloat16 (*wt)[32][40] = L ? sm.wt3 : sm.wt2;
                const float (*bb)[32] = L ? sm.b3 : sm.b2;
                #pragma unroll
                for (int nt = 0; nt < 4; nt++) {
                    const int n = nt * 8 + g;
                    const float2 bias = *(const float2*)&bb[m][nt * 8 + 2 * tc];
                    const uint32_t b00 = *(const uint32_t*)&wt[m][n][2 * tc];
                    const uint32_t b01 = *(const uint32_t*)&wt[m][n][2 * tc + 8];
                    const uint32_t b10 = *(const uint32_t*)&wt[m][n][2 * tc + 16];
                    const uint32_t b11 = *(const uint32_t*)&wt[m][n][2 * tc + 24];
                    #pragma unroll
                    for (int mt = 0; mt < 2; mt++) {
                        mma16816(d[m][mt][nt],
                                 A2[m][mt][0][0], A2[m][mt][0][1], A2[m][mt][0][2], A2[m][mt][0][3],
                                 b00, b01, bias.x, bias.y, bias.x, bias.y);
                        mma16816(d[m][mt][nt],
                                 A2[m][mt][1][0], A2[m][mt][1][1], A2[m][mt][1][2], A2[m][mt][1][3],
                                 b10, b11,
                                 d[m][mt][nt][0], d[m][mt][nt][1], d[m][mt][nt][2], d[m][mt][nt][3]);
                    }
                }
            }
        }

        // ---- Layer 4 as mma (both muscles) ----
        #pragma unroll
        for (int m = 0; m < 2; m++) {
            #pragma unroll
            for (int mt = 0; mt < 2; mt++) {
                #pragma unroll
                for (int kt = 0; kt < 2; kt++) {
                    const int na = 2 * kt, nb = 2 * kt + 1;
                    A2[m][mt][kt][0] = lkpk(d[m][mt][na][0], d[m][mt][na][1]);
                    A2[m][mt][kt][1] = lkpk(d[m][mt][na][2], d[m][mt][na][3]);
                    A2[m][mt][kt][2] = lkpk(d[m][mt][nb][0], d[m][mt][nb][1]);
                    A2[m][mt][kt][3] = lkpk(d[m][mt][nb][2], d[m][mt][nb][3]);
                }
            }
        }
        float d4[2][2][4];
        #pragma unroll
        for (int m = 0; m < 2; m++) {
            #pragma unroll
            for (int mt = 0; mt < 2; mt++) {
                mma16816(d4[m][mt],
                         A2[m][mt][0][0], A2[m][mt][0][1], A2[m][mt][0][2], A2[m][mt][0][3],
                         w4f[m][0], w4f[m][1], 0.f, 0.f, 0.f, 0.f);
                mma16816(d4[m][mt],
                         A2[m][mt][1][0], A2[m][mt][1][1], A2[m][mt][1][2], A2[m][mt][1][3],
                         w4f[m][2], w4f[m][3],
                         d4[m][mt][0], d4[m][mt][1], d4[m][mt][2], d4[m][mt][3]);
            }
        }

        // ---- distribute dots + physics ----
        float Kt = 0.f, Bs = 0.f;
        const int srcl = g * 4;
        #pragma unroll
        for (int m = 0; m < 2; m++) {
            const float v00 = __shfl_sync(0xffffffffu, d4[m][0][0], srcl);
            const float v02 = __shfl_sync(0xffffffffu, d4[m][0][2], srcl);
            const float v10 = __shfl_sync(0xffffffffu, d4[m][1][0], srcl);
            const float v12 = __shfl_sync(0xffffffffu, d4[m][1][2], srcl);
            const float o4 = (tc & 2) ? ((tc & 1) ? v12 : v10)
                                      : ((tc & 1) ? v02 : v00);
            const float nn = tanh_fast(o4 + sm.b4[m]) * NN_RATIO;

            const float Msm = __ldg(Ms + m);
            const float k0  = __ldg(K0s + m);
            const float k1  = __ldg(K1s + m);
            const float l0  = __ldg(L0s + m);
            const float l1  = __ldg(L1s + m);
            const float amv = m ? al1 : al0;
            const float lo  = ss.x * Msm;
            const float Km  = fmaf(k1, amv, k0);
            Kt = fmaf(Km, Msm * Msm, Kt);
            const float BF = Km * (l0 + l1 * amv - fabsf(lo))
                           + k1 * l1 * amv * amv * nn;
            Bs = fmaf(BF, Msm, Bs);
        }

        const float2 rr = integrate(ss.x, ss.y, Kt, Bs, invI0, I0, B0p, K0p);
        out[e] = rr.x;
        ((float2*)(out + B))[e] = rr;
    }
}

extern "C" void kernel_launch(void* const* d_in, const int* in_sizes, int n_in,
                              void* d_out, int out_size) {
    const float* SS     = (const float*)d_in[0];
    const float* Alphas = (const float*)d_in[1];
    const float* K0s    = (const float*)d_in[2];
    const float* K1s    = (const float*)d_in[3];
    const float* L0s    = (const float*)d_in[4];
    const float* L1s    = (const float*)d_in[5];
    const float* Ms     = (const float*)d_in[6];
    const float* I_p    = (const float*)d_in[7];
    const float* B_p    = (const float*)d_in[8];
    const float* K_p    = (const float*)d_in[9];
    const float* W1     = (const float*)d_in[10];
    const float* b1     = (const float*)d_in[11];
    const float* W2     = (const float*)d_in[12];
    const float* b2     = (const float*)d_in[13];
    const float* W3     = (const float*)d_in[14];
    const float* b3     = (const float*)d_in[15];
    const float* W4     = (const float*)d_in[16];
    const float* b4     = (const float*)d_in[17];
    float* out = (float*)d_out;

    const int B = in_sizes[0] / 2;
    const int grid = B / (128 * PASSES);
    joint_mma_kernel<<<grid, THREADS>>>(SS, Alphas, K0s, K1s, L0s, L1s, Ms,
                                        I_p, B_p, K_p, W1, b1, W2, b2, W3, b3,
                                        W4, b4, out, B);
}

// round 16
// speedup vs baseline: 1.0435x; 1.0435x over previous
#include <cuda_runtime.h>
#include <cuda_bf16.h>
#include <cstdint>

#define DT       0.0166667f
#define SLOPE    0.01f
#define NN_RATIO 0.5f
#define THREADS  128
#define PASSES   4

// bf16x2 constant 0.01 (0x3C24 per half)
#define SLOPE2   0x3C243C24u

struct __align__(16) Smem {
    __nv_bfloat16 wt1[2][32][20];   // W1^T: k<2 *Ms, k==2 alpha row, k==3 = b1, rest 0
    __nv_bfloat16 wt2[2][32][40];   // W2^T padded: [m][o][i]
    __nv_bfloat16 wt3[2][32][40];   // W3^T padded
    uint32_t w4b[2][16];            // w4 packed bf16x2
    float b2[2][32], b3[2][32], b4[2];
};

__device__ __forceinline__ float tanh_fast(float x) {
    float y; asm("tanh.approx.f32 %0, %1;" : "=f"(y) : "f"(x)); return y;
}
__device__ __forceinline__ uint32_t pkbf(float lo, float hi) {
    uint32_t r; asm("cvt.rn.bf16x2.f32 %0, %1, %2;" : "=r"(r) : "f"(hi), "f"(lo)); return r;
}
// packed leaky relu on bf16x2: max(x, 0.01*x)
__device__ __forceinline__ uint32_t lk2(uint32_t x) {
    uint32_t y, r;
    asm("mul.rn.bf16x2 %0, %1, %2;" : "=r"(y) : "r"(x), "r"(SLOPE2));
    asm("max.bf16x2 %0, %1, %2;"    : "=r"(r) : "r"(x), "r"(y));
    return r;
}
__device__ __forceinline__ uint32_t lkpk(float a, float b) { return lk2(pkbf(a, b)); }

__device__ __forceinline__ void mma16816(float* d,
    uint32_t a0, uint32_t a1, uint32_t a2, uint32_t a3,
    uint32_t b0, uint32_t b1,
    float c0, float c1, float c2, float c3)
{
    asm volatile(
        "mma.sync.aligned.m16n8k16.row.col.f32.bf16.bf16.f32 "
        "{%0,%1,%2,%3},{%4,%5,%6,%7},{%8,%9},{%10,%11,%12,%13};"
        : "=f"(d[0]), "=f"(d[1]), "=f"(d[2]), "=f"(d[3])
        : "r"(a0), "r"(a1), "r"(a2), "r"(a3), "r"(b0), "r"(b1),
          "f"(c0), "f"(c1), "f"(c2), "f"(c3));
}

// SSout = e^A*SS + phi1(A)*[0, B10*DT]^T  (closed form of the 6x6 expm)
// ||A|| <= ~0.12 -> 4 Taylor terms give ~2e-7 truncation
__device__ __forceinline__ float2 integrate(float ss0, float ss1, float Ktot, float Bsum,
                                            float invI0, float I0, float B0p, float K0p) {
    const float A10 = -(Ktot + K0p) * invI0;
    const float Dd  = 2.0f * sqrtf(Ktot * I0);
    const float A11 = -(Dd + B0p) * invI0;
    const float B10 = Bsum * invI0;
    const float a01 = DT, a10 = A10 * DT, a11 = A11 * DT;

    float T00 = 1.f, T01 = 0.f, T10 = 0.f, T11 = 1.f;
    float E00 = 1.f, E01 = 0.f, E10 = 0.f, E11 = 1.f;
    float P01 = 0.f, P11 = 1.f;
    #pragma unroll
    for (int k = 1; k <= 4; k++) {
        const float r   = 1.0f / (float)k;
        const float n00 = (T01 * a10) * r;
        const float n01 = (T00 * a01 + T01 * a11) * r;
        const float n10 = (T11 * a10) * r;
        const float n11 = (T10 * a01 + T11 * a11) * r;
        T00 = n00; T01 = n01; T10 = n10; T11 = n11;
        E00 += T00; E01 += T01; E10 += T10; E11 += T11;
        const float r2 = 1.0f / (float)(k + 1);
        P01 = fmaf(T01, r2, P01);
        P11 = fmaf(T11, r2, P11);
    }
    const float cx = B10 * DT;
    float2 o;
    o.x = E00 * ss0 + E01 * ss1 + P01 * cx;
    o.y = E10 * ss0 + E11 * ss1 + P11 * cx;
    return o;
}

__global__ void __launch_bounds__(THREADS, 5) joint_mma_kernel(
    const float* __restrict__ SS, const float* __restrict__ Alphas,
    const float* __restrict__ K0s, const float* __restrict__ K1s,
    const float* __restrict__ L0s, const float* __restrict__ L1s,
    const float* __restrict__ Ms,  const float* __restrict__ I_p,
    const float* __restrict__ B_p, const float* __restrict__ K_p,
    const float* __restrict__ W1, const float* __restrict__ b1g,
    const float* __restrict__ W2, const float* __restrict__ b2g,
    const float* __restrict__ W3, const float* __restrict__ b3g,
    const float* __restrict__ W4, const float* __restrict__ b4g,
    float* __restrict__ out, int B)
{
    __shared__ Smem sm;
    const int tid = threadIdx.x;

    // ---- Stage weights (transposed, bf16) ----
    // wt1 rows: k<2 = W1*Ms (Ms=+-1 exact), k==2 = alpha row, k==3 = b1
    // (bias rides K slot 3; A-fragment supplies constant 1.0 there), k>=4 zero
    for (int idx = tid; idx < 1024; idx += THREADS) {
        const int k = idx & 15, o = (idx >> 4) & 31, m = idx >> 9;
        float v = 0.0f;
        if (k < 3) {
            v = W1[m * 96 + k * 32 + o];
            if (k < 2) v *= __ldg(Ms + m);
        } else if (k == 3) {
            v = b1g[m * 32 + o];
        }
        sm.wt1[m][o][k] = __float2bfloat16(v);
    }
    for (int idx = tid; idx < 2048; idx += THREADS) {
        const int o = idx & 31, i = (idx >> 5) & 31, m = idx >> 10;
        sm.wt2[m][o][i] = __float2bfloat16(W2[idx]);
        sm.wt3[m][o][i] = __float2bfloat16(W3[idx]);
    }
    for (int idx = tid; idx < 64; idx += THREADS) {
        const int m = idx >> 5, o = idx & 31;
        sm.b2[m][o] = b2g[idx];
        sm.b3[m][o] = b3g[idx];
    }
    if (tid < 32) {
        const int m = tid >> 4, j = tid & 15;
        sm.w4b[m][j] = pkbf(W4[m * 32 + 2 * j], W4[m * 32 + 2 * j + 1]);
    }
    if (tid < 2) sm.b4[tid] = b4g[tid];
    __syncthreads();

    const int l  = tid & 31, w = tid >> 5;
    const int g  = l >> 2, tc = l & 3;
    const int own_row = g + 8 * tc;

    const float I0  = __ldg(I_p), B0p = __ldg(B_p), K0p = __ldg(K_p);
    const float invI0 = 1.0f / I0;

    // L4 B-fragments with w4 REPLICATED across all 8 N-columns:
    // B-frag col = group g, so every lane loads the same per-tc values.
    // Result: every D column holds the row-dot -> no distribution shuffles.
    uint32_t w4f[2][4];
    #pragma unroll
    for (int m = 0; m < 2; m++) {
        w4f[m][0] = sm.w4b[m][tc];
        w4f[m][1] = sm.w4b[m][tc + 4];
        w4f[m][2] = sm.w4b[m][tc + 8];
        w4f[m][3] = sm.w4b[m][tc + 12];
    }

    #pragma unroll 1
    for (int p = 0; p < PASSES; p++) {
        const int ebase = (blockIdx.x * PASSES + p) * 128 + w * 32;
        const int e = ebase + own_row;
        const float2 ss = ((const float2*)SS)[e];
        const float2 al = ((const float2*)Alphas)[e];
        const float al0 = __saturatef(al.x);
        const float al1 = __saturatef(al.y);

        // pack to bf16x2 BEFORE shuffling: 8 SHFL
        const uint32_t ssb = pkbf(ss.x, ss.y);
        const uint32_t amb = pkbf(al0, al1);
        uint32_t ssj[4], amj[4];
        #pragma unroll
        for (int j = 0; j < 4; j++) {
            const int src = (l & ~3) + j;
            ssj[j] = __shfl_sync(0xffffffffu, ssb, src);
            amj[j] = __shfl_sync(0xffffffffu, amb, src);
        }

        float Kt = 0.f, Bs = 0.f;

        #pragma unroll
        for (int m = 0; m < 2; m++) {
            // ---- Layer 1 A-fragments: X rows = [ss0, ss1, alpha_m, 1.0] ----
            // tc==0 -> (ss0,ss1) @ k0,k1 ; tc==1 -> (alpha_m, 1.0) @ k2,k3
            uint32_t A1f[2][2];
            #pragma unroll
            for (int mt = 0; mt < 2; mt++) {
                #pragma unroll
                for (int jj = 0; jj < 2; jj++) {
                    const int j = 2 * mt + jj;
                    uint32_t v = 0u;
                    if (tc == 0)      v = ssj[j];
                    else if (tc == 1) v = (m ? (amj[j] >> 16) : (amj[j] & 0xFFFFu))
                                          | 0x3F800000u;
                    A1f[mt][jj] = v;
                }
            }

            float d[2][4][4];

            // ---- Layer 1 mma: K=16, C=0 (bias folded into B) ----
            #pragma unroll
            for (int nt = 0; nt < 4; nt++) {
                const int n = nt * 8 + g;
                const uint32_t b0  = *(const uint32_t*)&sm.wt1[m][n][2 * tc];
                const uint32_t b1f = *(const uint32_t*)&sm.wt1[m][n][2 * tc + 8];
                #pragma unroll
                for (int mt = 0; mt < 2; mt++)
                    mma16816(d[mt][nt], A1f[mt][0], A1f[mt][1], 0u, 0u,
                             b0, b1f, 0.f, 0.f, 0.f, 0.f);
            }

            // ---- Layers 2 and 3 ----
            uint32_t A2[2][2][4];
            #pragma unroll
            for (int L = 0; L < 2; L++) {
                // packed-bf16 leaky + repack: D(m16n8) layout == A(m16k16) layout
                #pragma unroll
                for (int mt = 0; mt < 2; mt++) {
                    #pragma unroll
                    for (int kt = 0; kt < 2; kt++) {
                        const int na = 2 * kt, nb = 2 * kt + 1;
                        A2[mt][kt][0] = lkpk(d[mt][na][0], d[mt][na][1]);
                        A2[mt][kt][1] = lkpk(d[mt][na][2], d[mt][na][3]);
                        A2[mt][kt][2] = lkpk(d[mt][nb][0], d[mt][nb][1]);
                        A2[mt][kt][3] = lkpk(d[mt][nb][2], d[mt][nb][3]);
                    }
                }
                const __nv_bfloat16 (*wt)[32][40] = L ? sm.wt3 : sm.wt2;
                const float (*bb)[32] = L ? sm.b3 : sm.b2;
                #pragma unroll
                for (int nt = 0; nt < 4; nt++) {
                    const int n = nt * 8 + g;
                    const float2 bias = *(const float2*)&bb[m][nt * 8 + 2 * tc];
                    const uint32_t b00 = *(const uint32_t*)&wt[m][n][2 * tc];
                    const uint32_t b01 = *(const uint32_t*)&wt[m][n][2 * tc + 8];
                    const uint32_t b10 = *(const uint32_t*)&wt[m][n][2 * tc + 16];
                    const uint32_t b11 = *(const uint32_t*)&wt[m][n][2 * tc + 24];
                    #pragma unroll
                    for (int mt = 0; mt < 2; mt++) {
                        mma16816(d[mt][nt], A2[mt][0][0], A2[mt][0][1], A2[mt][0][2], A2[mt][0][3],
                                 b00, b01, bias.x, bias.y, bias.x, bias.y);
                        mma16816(d[mt][nt], A2[mt][1][0], A2[mt][1][1], A2[mt][1][2], A2[mt][1][3],
                                 b10, b11, d[mt][nt][0], d[mt][nt][1], d[mt][nt][2], d[mt][nt][3]);
                    }
                }
            }

            // ---- Layer 4 as mma: leaky(L3) @ w4 replicated across N ----
            #pragma unroll
            for (int mt = 0; mt < 2; mt++) {
                #pragma unroll
                for (int kt = 0; kt < 2; kt++) {
                    const int na = 2 * kt, nb = 2 * kt + 1;
                    A2[mt][kt][0] = lkpk(d[mt][na][0], d[mt][na][1]);
                    A2[mt][kt][1] = lkpk(d[mt][na][2], d[mt][na][3]);
                    A2[mt][kt][2] = lkpk(d[mt][nb][0], d[mt][nb][1]);
                    A2[mt][kt][3] = lkpk(d[mt][nb][2], d[mt][nb][3]);
                }
            }
            float d4[2][4];
            #pragma unroll
            for (int mt = 0; mt < 2; mt++) {
                mma16816(d4[mt], A2[mt][0][0], A2[mt][0][1], A2[mt][0][2], A2[mt][0][3],
                         w4f[m][0], w4f[m][1], 0.f, 0.f, 0.f, 0.f);
                mma16816(d4[mt], A2[mt][1][0], A2[mt][1][1], A2[mt][1][2], A2[mt][1][3],
                         w4f[m][2], w4f[m][3], d4[mt][0], d4[mt][1], d4[mt][2], d4[mt][3]);
            }
            // every column equal -> own row lives in OWN registers:
            // tile = tc>>1, reg = 2*(tc&1)
            const float o4 = (tc & 2) ? ((tc & 1) ? d4[1][2] : d4[1][0])
                                      : ((tc & 1) ? d4[0][2] : d4[0][0]);
            const float nn = tanh_fast(o4 + sm.b4[m]) * NN_RATIO;

            // ---- physics for own element (fp32, uniform scalars via L2) ----
            const float Msm = __ldg(Ms + m);
            const float k0  = __ldg(K0s + m);
            const float k1  = __ldg(K1s + m);
            const float l0  = __ldg(L0s + m);
            const float l1  = __ldg(L1s + m);
            const float amv = m ? al1 : al0;
            const float lo  = ss.x * Msm;
            const float Km  = fmaf(k1, amv, k0);
            Kt = fmaf(Km, Msm * Msm, Kt);
            const float BF = Km * (l0 + l1 * amv - fabsf(lo))
                           + k1 * l1 * amv * amv * nn;
            Bs = fmaf(BF, Msm, Bs);
        }

        const float2 rr = integrate(ss.x, ss.y, Kt, Bs, invI0, I0, B0p, K0p);
        out[e] = rr.x;
        ((float2*)(out + B))[e] = rr;
    }
}

extern "C" void kernel_launch(void* const* d_in, const int* in_sizes, int n_in,
                              void* d_out, int out_size) {
    const float* SS     = (const float*)d_in[0];
    const float* Alphas = (const float*)d_in[1];
    const float* K0s    = (const float*)d_in[2];
    const float* K1s    = (const float*)d_in[3];
    const float* L0s    = (const float*)d_in[4];
    const float* L1s    = (const float*)d_in[5];
    const float* Ms     = (const float*)d_in[6];
    const float* I_p    = (const float*)d_in[7];
    const float* B_p    = (const float*)d_in[8];
    const float* K_p    = (const float*)d_in[9];
    const float* W1     = (const float*)d_in[10];
    const float* b1     = (const float*)d_in[11];
    const float* W2     = (const float*)d_in[12];
    const float* b2     = (const float*)d_in[13];
    const float* W3     = (const float*)d_in[14];
    const float* b3     = (const float*)d_in[15];
    const float* W4     = (const float*)d_in[16];
    const float* b4     = (const float*)d_in[17];
    float* out = (float*)d_out;

    const int B = in_sizes[0] / 2;
    const int grid = B / (128 * PASSES);
    joint_mma_kernel<<<grid, THREADS>>>(SS, Alphas, K0s, K1s, L0s, L1s, Ms,
                                        I_p, B_p, K_p, W1, b1, W2, b2, W3, b3,
                                        W4, b4, out, B);
}

// round 17
// speedup vs baseline: 1.1090x; 1.0628x over previous
#include <cuda_runtime.h>
#include <cuda_fp16.h>
#include <cstdint>

#define DT       0.0166667f
#define SLOPE    0.01f
#define NN_RATIO 0.5f
#define THREADS  128
#define PASSES   4

// f16x2 constant 0.01 (0x211F per half)
#define SLOPE2H  0x211F211Fu

struct __align__(16) Smem {
    __half wt1[2][32][24];   // W1^T: k<2 *Ms, k==2 alpha row, k==3 = b1, rest 0
    __half wt2[2][32][40];   // W2^T padded: [m][o][i]
    __half wt3[2][32][40];   // W3^T padded
    uint32_t w4h[2][16];     // w4 packed f16x2
    uint32_t bb2[2][16];     // b2 packed f16x2 (col pairs)
    uint32_t bb3[2][16];     // b3 packed f16x2
    float b4[2];
};

__device__ __forceinline__ float tanh_fast(float x) {
    float y; asm("tanh.approx.f32 %0, %1;" : "=f"(y) : "f"(x)); return y;
}
// pack two f32 -> f16x2 (lo in low half)
__device__ __forceinline__ uint32_t pkhf(float lo, float hi) {
    uint32_t r; asm("cvt.rn.f16x2.f32 %0, %1, %2;" : "=r"(r) : "f"(hi), "f"(lo)); return r;
}
// packed leaky relu on f16x2: max(x, 0.01*x) — no conversions, D==A layout
__device__ __forceinline__ uint32_t lk2h(uint32_t x) {
    uint32_t y, r;
    asm("mul.rn.f16x2 %0, %1, %2;" : "=r"(y) : "r"(x), "r"(SLOPE2H));
    asm("max.f16x2 %0, %1, %2;"    : "=r"(r) : "r"(x), "r"(y));
    return r;
}

// f16-accum HMMA: D,C are 2x f16x2
__device__ __forceinline__ void mmah(uint32_t* d,
    uint32_t a0, uint32_t a1, uint32_t a2, uint32_t a3,
    uint32_t b0, uint32_t b1, uint32_t c0, uint32_t c1)
{
    asm volatile(
        "mma.sync.aligned.m16n8k16.row.col.f16.f16.f16.f16 "
        "{%0,%1},{%2,%3,%4,%5},{%6,%7},{%8,%9};"
        : "=r"(d[0]), "=r"(d[1])
        : "r"(a0), "r"(a1), "r"(a2), "r"(a3), "r"(b0), "r"(b1),
          "r"(c0), "r"(c1));
}

// SSout = e^A*SS + phi1(A)*[0, B10*DT]^T  (closed form of the 6x6 expm)
__device__ __forceinline__ float2 integrate(float ss0, float ss1, float Ktot, float Bsum,
                                            float invI0, float I0, float B0p, float K0p) {
    const float A10 = -(Ktot + K0p) * invI0;
    const float Dd  = 2.0f * sqrtf(Ktot * I0);
    const float A11 = -(Dd + B0p) * invI0;
    const float B10 = Bsum * invI0;
    const float a01 = DT, a10 = A10 * DT, a11 = A11 * DT;

    float T00 = 1.f, T01 = 0.f, T10 = 0.f, T11 = 1.f;
    float E00 = 1.f, E01 = 0.f, E10 = 0.f, E11 = 1.f;
    float P01 = 0.f, P11 = 1.f;
    #pragma unroll
    for (int k = 1; k <= 4; k++) {
        const float r   = 1.0f / (float)k;
        const float n00 = (T01 * a10) * r;
        const float n01 = (T00 * a01 + T01 * a11) * r;
        const float n10 = (T11 * a10) * r;
        const float n11 = (T10 * a01 + T11 * a11) * r;
        T00 = n00; T01 = n01; T10 = n10; T11 = n11;
        E00 += T00; E01 += T01; E10 += T10; E11 += T11;
        const float r2 = 1.0f / (float)(k + 1);
        P01 = fmaf(T01, r2, P01);
        P11 = fmaf(T11, r2, P11);
    }
    const float cx = B10 * DT;
    float2 o;
    o.x = E00 * ss0 + E01 * ss1 + P01 * cx;
    o.y = E10 * ss0 + E11 * ss1 + P11 * cx;
    return o;
}

__global__ void __launch_bounds__(THREADS, 6) joint_mma_kernel(
    const float* __restrict__ SS, const float* __restrict__ Alphas,
    const float* __restrict__ K0s, const float* __restrict__ K1s,
    const float* __restrict__ L0s, const float* __restrict__ L1s,
    const float* __restrict__ Ms,  const float* __restrict__ I_p,
    const float* __restrict__ B_p, const float* __restrict__ K_p,
    const float* __restrict__ W1, const float* __restrict__ b1g,
    const float* __restrict__ W2, const float* __restrict__ b2g,
    const float* __restrict__ W3, const float* __restrict__ b3g,
    const float* __restrict__ W4, const float* __restrict__ b4g,
    float* __restrict__ out, int B)
{
    __shared__ Smem sm;
    const int tid = threadIdx.x;

    // ---- Stage weights (transposed, f16) ----
    // wt1 rows: k<2 = W1*Ms (Ms=+-1 exact), k==2 = alpha row, k==3 = b1
    // (bias rides K slot 3; A-fragment supplies constant 1.0 there), k>=4 zero
    for (int idx = tid; idx < 1536; idx += THREADS) {
        const int k = idx % 24, o = (idx / 24) & 31, m = idx / 768;
        float v = 0.0f;
        if (k < 3) {
            v = W1[m * 96 + k * 32 + o];
            if (k < 2) v *= __ldg(Ms + m);
        } else if (k == 3) {
            v = b1g[m * 32 + o];
        }
        sm.wt1[m][o][k] = __float2half(v);
    }
    for (int idx = tid; idx < 2048; idx += THREADS) {
        const int o = idx & 31, i = (idx >> 5) & 31, m = idx >> 10;
        sm.wt2[m][o][i] = __float2half(W2[idx]);
        sm.wt3[m][o][i] = __float2half(W3[idx]);
    }
    if (tid < 32) {
        const int m = tid >> 4, j = tid & 15;
        sm.w4h[m][j] = pkhf(W4[m * 32 + 2 * j],  W4[m * 32 + 2 * j + 1]);
        sm.bb2[m][j] = pkhf(b2g[m * 32 + 2 * j], b2g[m * 32 + 2 * j + 1]);
        sm.bb3[m][j] = pkhf(b3g[m * 32 + 2 * j], b3g[m * 32 + 2 * j + 1]);
    }
    if (tid < 2) sm.b4[tid] = b4g[tid];
    __syncthreads();

    const int l  = tid & 31, w = tid >> 5;
    const int g  = l >> 2, tc = l & 3;
    const int own_row = g + 8 * tc;

    const float I0  = __ldg(I_p), B0p = __ldg(B_p), K0p = __ldg(K_p);
    const float invI0 = 1.0f / I0;

    // L4 B-fragments with w4 REPLICATED across all 8 N-columns (no distribution
    // shuffles needed; every D column holds the row-dot)
    uint32_t w4f[2][4];
    #pragma unroll
    for (int m = 0; m < 2; m++) {
        w4f[m][0] = sm.w4h[m][tc];
        w4f[m][1] = sm.w4h[m][tc + 4];
        w4f[m][2] = sm.w4h[m][tc + 8];
        w4f[m][3] = sm.w4h[m][tc + 12];
    }

    #pragma unroll 1
    for (int p = 0; p < PASSES; p++) {
        const int ebase = (blockIdx.x * PASSES + p) * 128 + w * 32;
        const int e = ebase + own_row;
        const float2 ss = ((const float2*)SS)[e];
        const float2 al = ((const float2*)Alphas)[e];
        const float al0 = __saturatef(al.x);
        const float al1 = __saturatef(al.y);

        // pack to f16x2 BEFORE shuffling: 8 SHFL
        const uint32_t ssb = pkhf(ss.x, ss.y);
        const uint32_t amb = pkhf(al0, al1);
        uint32_t ssj[4], amj[4];
        #pragma unroll
        for (int j = 0; j < 4; j++) {
            const int src = (l & ~3) + j;
            ssj[j] = __shfl_sync(0xffffffffu, ssb, src);
            amj[j] = __shfl_sync(0xffffffffu, amb, src);
        }

        float Kt = 0.f, Bs = 0.f;

        #pragma unroll
        for (int m = 0; m < 2; m++) {
            // ---- Layer 1 A-fragments: X rows = [ss0, ss1, alpha_m, 1.0] ----
            // tc==0 -> (ss0,ss1) @ k0,k1 ; tc==1 -> (alpha_m, 1.0) @ k2,k3
            uint32_t A1f[2][2];
            #pragma unroll
            for (int mt = 0; mt < 2; mt++) {
                #pragma unroll
                for (int jj = 0; jj < 2; jj++) {
                    const int j = 2 * mt + jj;
                    uint32_t v = 0u;
                    if (tc == 0)      v = ssj[j];
                    else if (tc == 1) v = (m ? (amj[j] >> 16) : (amj[j] & 0xFFFFu))
                                          | 0x3C000000u;   // f16 1.0 in high half
                    A1f[mt][jj] = v;
                }
            }

            uint32_t dh[2][4][2];   // f16x2 D: [mt][nt][reg]

            // ---- Layer 1 mma: K=16, C=0 (bias folded into B) ----
            #pragma unroll
            for (int nt = 0; nt < 4; nt++) {
                const int n = nt * 8 + g;
                const uint32_t b0  = *(const uint32_t*)&sm.wt1[m][n][2 * tc];
                const uint32_t b1f = *(const uint32_t*)&sm.wt1[m][n][2 * tc + 8];
                #pragma unroll
                for (int mt = 0; mt < 2; mt++)
                    mmah(dh[mt][nt], A1f[mt][0], A1f[mt][1], 0u, 0u,
                         b0, b1f, 0u, 0u);
            }

            // ---- Layers 2 and 3 ----
            uint32_t A2[2][2][4];
            #pragma unroll
            for (int L = 0; L < 2; L++) {
                // packed leaky: f16 D layout == f16 A layout, zero conversions
                #pragma unroll
                for (int mt = 0; mt < 2; mt++) {
                    #pragma unroll
                    for (int kt = 0; kt < 2; kt++) {
                        const int na = 2 * kt, nb = 2 * kt + 1;
                        A2[mt][kt][0] = lk2h(dh[mt][na][0]);
                        A2[mt][kt][1] = lk2h(dh[mt][na][1]);
                        A2[mt][kt][2] = lk2h(dh[mt][nb][0]);
                        A2[mt][kt][3] = lk2h(dh[mt][nb][1]);
                    }
                }
                const __half (*wt)[32][40] = L ? sm.wt3 : sm.wt2;
                const uint32_t (*bb)[16] = L ? sm.bb3 : sm.bb2;
                #pragma unroll
                for (int nt = 0; nt < 4; nt++) {
                    const int n = nt * 8 + g;
                    const uint32_t bias = bb[m][nt * 4 + tc];
                    const uint32_t b00 = *(const uint32_t*)&wt[m][n][2 * tc];
                    const uint32_t b01 = *(const uint32_t*)&wt[m][n][2 * tc + 8];
                    const uint32_t b10 = *(const uint32_t*)&wt[m][n][2 * tc + 16];
                    const uint32_t b11 = *(const uint32_t*)&wt[m][n][2 * tc + 24];
                    #pragma unroll
                    for (int mt = 0; mt < 2; mt++) {
                        mmah(dh[mt][nt], A2[mt][0][0], A2[mt][0][1], A2[mt][0][2], A2[mt][0][3],
                             b00, b01, bias, bias);
                        mmah(dh[mt][nt], A2[mt][1][0], A2[mt][1][1], A2[mt][1][2], A2[mt][1][3],
                             b10, b11, dh[mt][nt][0], dh[mt][nt][1]);
                    }
                }
            }

            // ---- Layer 4 as mma: leaky(L3) @ w4 replicated across N ----
            #pragma unroll
            for (int mt = 0; mt < 2; mt++) {
                #pragma unroll
                for (int kt = 0; kt < 2; kt++) {
                    const int na = 2 * kt, nb = 2 * kt + 1;
                    A2[mt][kt][0] = lk2h(dh[mt][na][0]);
                    A2[mt][kt][1] = lk2h(dh[mt][na][1]);
                    A2[mt][kt][2] = lk2h(dh[mt][nb][0]);
                    A2[mt][kt][3] = lk2h(dh[mt][nb][1]);
                }
            }
            uint32_t d4[2][2];
            #pragma unroll
            for (int mt = 0; mt < 2; mt++) {
                mmah(d4[mt], A2[mt][0][0], A2[mt][0][1], A2[mt][0][2], A2[mt][0][3],
                     w4f[m][0], w4f[m][1], 0u, 0u);
                mmah(d4[mt], A2[mt][1][0], A2[mt][1][1], A2[mt][1][2], A2[mt][1][3],
                     w4f[m][2], w4f[m][3], d4[mt][0], d4[mt][1]);
            }
            // own row (g + 8*tc): tile tc>>1, reg tc&1 (row g vs g+8), low half
            const uint32_t o4r = (tc & 2) ? d4[1][tc & 1] : d4[0][tc & 1];
            const unsigned short o4lo = (unsigned short)(o4r & 0xFFFFu);
            const float o4 = __half2float(*reinterpret_cast<const __half*>(&o4lo));
            const float nn = tanh_fast(o4 + sm.b4[m]) * NN_RATIO;

            // ---- physics for own element (fp32, uniform scalars via L2) ----
            const float Msm = __ldg(Ms + m);
            const float k0  = __ldg(K0s + m);
            const float k1  = __ldg(K1s + m);
            const float l0  = __ldg(L0s + m);
            const float l1  = __ldg(L1s + m);
            const float amv = m ? al1 : al0;
            const float lo  = ss.x * Msm;
            const float Km  = fmaf(k1, amv, k0);
            Kt = fmaf(Km, Msm * Msm, Kt);
            const float BF = Km * (l0 + l1 * amv - fabsf(lo))
                           + k1 * l1 * amv * amv * nn;
            Bs = fmaf(BF, Msm, Bs);
        }

        const float2 rr = integrate(ss.x, ss.y, Kt, Bs, invI0, I0, B0p, K0p);
        out[e] = rr.x;
        ((float2*)(out + B))[e] = rr;
    }
}

extern "C" void kernel_launch(void* const* d_in, const int* in_sizes, int n_in,
                              void* d_out, int out_size) {
    const float* SS     = (const float*)d_in[0];
    const float* Alphas = (const float*)d_in[1];
    const float* K0s    = (const float*)d_in[2];
    const float* K1s    = (const float*)d_in[3];
    const float* L0s    = (const float*)d_in[4];
    const float* L1s    = (const float*)d_in[5];
    const float* Ms     = (const float*)d_in[6];
    const float* I_p    = (const float*)d_in[7];
    const float* B_p    = (const float*)d_in[8];
    const float* K_p    = (const float*)d_in[9];
    const float* W1     = (const float*)d_in[10];
    const float* b1     = (const float*)d_in[11];
    const float* W2     = (const float*)d_in[12];
    const float* b2     = (const float*)d_in[13];
    const float* W3     = (const float*)d_in[14];
    const float* b3     = (const float*)d_in[15];
    const float* W4     = (const float*)d_in[16];
    const float* b4     = (const float*)d_in[17];
    float* out = (float*)d_out;

    const int B = in_sizes[0] / 2;
    const int grid = B / (128 * PASSES);
    joint_mma_kernel<<<grid, THREADS>>>(SS, Alphas, K0s, K1s, L0s, L1s, Ms,
                                        I_p, B_p, K_p, W1, b1, W2, b2, W3, b3,
                                        W4, b4, out, B);
}